// round 12
// baseline (speedup 1.0000x reference)
#include <cuda_runtime.h>
#include <cstdint>

// AutoencoderInverseAffine:
//   out[n] = (samples[n] - mus[symb,comp]) / psi[comp] + mus_orig[symb,comp]
// Refactored to one FMA per element:
//   out[n][d] = samples[n][d] * a[comp][d] + b[symb][comp][d]
//   a[comp][d]       = 1/psi[comp*8+d]
//   b[symb][comp][d] = mus_orig[symb*32+comp*8+d] - mus[symb*32+comp*8+d]*a[comp][d]
//
// Shapes: N_SAMP=8388608, N_DIM=8, N_COMP=4, NX_UNIQUE=16.
// 4 rows/thread: 8x LDG.128 (samples) + 2x LDG.128 (int4 indices) front-batched,
// 8x STG.128 out. Tables (2.2 KB) built in shared per block.

#define N_DIM   8
#define N_COMP  4
#define NX      16
#define AD      (N_COMP * N_DIM)        // 32
#define TBL     (NX * AD)               // 512
#define BLOCK   256
#define RPT     4                        // rows per thread

__global__ void __launch_bounds__(BLOCK)
inv_affine_kernel(const float4* __restrict__ samples,   // n*2 float4
                  const float*  __restrict__ mus_orig,  // 512
                  const float*  __restrict__ mus,       // 512
                  const float*  __restrict__ psi,       // 32
                  const int*    __restrict__ idx_symb,  // n
                  const int*    __restrict__ idx_comp,  // n
                  float4*       __restrict__ out,       // n*2 float4
                  int n)
{
    __shared__ __align__(16) float s_a[AD];   // 1/psi
    __shared__ __align__(16) float s_b[TBL];  // mus_orig - mus/psi

    const int tid = threadIdx.x;

    #pragma unroll
    for (int i = tid; i < TBL; i += BLOCK) {
        const int j = i & (AD - 1);
        const float ip = __frcp_rn(psi[j]);
        s_b[i] = fmaf(-mus[i], ip, mus_orig[i]);
    }
    if (tid < AD) s_a[tid] = __frcp_rn(psi[tid]);
    __syncthreads();

    const int group = blockIdx.x * BLOCK + tid;  // rows 4*group .. 4*group+3
    const int row0  = group * RPT;               // multiple of 4 -> int4 loads aligned

    if (row0 + RPT <= n) {
        // ---- fast path: front-batch all 10 independent global loads ----
        float4 s[2 * RPT];
        #pragma unroll
        for (int r = 0; r < RPT; r++) {
            s[2 * r + 0] = __ldcs(&samples[2 * (row0 + r) + 0]);
            s[2 * r + 1] = __ldcs(&samples[2 * (row0 + r) + 1]);
        }
        const int4 symb4 = __ldcs((const int4*)&idx_symb[row0]);
        const int4 comp4 = __ldcs((const int4*)&idx_comp[row0]);

        const int sy[RPT] = {symb4.x, symb4.y, symb4.z, symb4.w};
        const int cp[RPT] = {comp4.x, comp4.y, comp4.z, comp4.w};

        #pragma unroll
        for (int r = 0; r < RPT; r++) {
            const int ao = cp[r] * N_DIM;
            const int bo = sy[r] * AD + ao;
            const float4 a0 = *(const float4*)&s_a[ao];
            const float4 a1 = *(const float4*)&s_a[ao + 4];
            const float4 b0 = *(const float4*)&s_b[bo];
            const float4 b1 = *(const float4*)&s_b[bo + 4];
            float4 o0, o1;
            o0.x = fmaf(s[2*r+0].x, a0.x, b0.x);
            o0.y = fmaf(s[2*r+0].y, a0.y, b0.y);
            o0.z = fmaf(s[2*r+0].z, a0.z, b0.z);
            o0.w = fmaf(s[2*r+0].w, a0.w, b0.w);
            o1.x = fmaf(s[2*r+1].x, a1.x, b1.x);
            o1.y = fmaf(s[2*r+1].y, a1.y, b1.y);
            o1.z = fmaf(s[2*r+1].z, a1.z, b1.z);
            o1.w = fmaf(s[2*r+1].w, a1.w, b1.w);
            __stcs(&out[2 * (row0 + r) + 0], o0);
            __stcs(&out[2 * (row0 + r) + 1], o1);
        }
    } else {
        // ---- tail: scalar per-row (n % 4 != 0 safety; untaken at n=8388608) ----
        for (int row = row0; row < n; row++) {
            const float4 s0 = __ldcs(&samples[2 * row + 0]);
            const float4 s1 = __ldcs(&samples[2 * row + 1]);
            const int symb = idx_symb[row];
            const int comp = idx_comp[row];
            const int ao = comp * N_DIM;
            const int bo = symb * AD + ao;
            const float4 a0 = *(const float4*)&s_a[ao];
            const float4 a1 = *(const float4*)&s_a[ao + 4];
            const float4 b0 = *(const float4*)&s_b[bo];
            const float4 b1 = *(const float4*)&s_b[bo + 4];
            float4 o0, o1;
            o0.x = fmaf(s0.x, a0.x, b0.x); o0.y = fmaf(s0.y, a0.y, b0.y);
            o0.z = fmaf(s0.z, a0.z, b0.z); o0.w = fmaf(s0.w, a0.w, b0.w);
            o1.x = fmaf(s1.x, a1.x, b1.x); o1.y = fmaf(s1.y, a1.y, b1.y);
            o1.z = fmaf(s1.z, a1.z, b1.z); o1.w = fmaf(s1.w, a1.w, b1.w);
            __stcs(&out[2 * row + 0], o0);
            __stcs(&out[2 * row + 1], o1);
        }
    }
}

extern "C" void kernel_launch(void* const* d_in, const int* in_sizes, int n_in,
                              void* d_out, int out_size)
{
    // metadata order: samples_, mus_orig_, mus_, psi_c_, idx_symb_, idx_comp_, n_samp_, n_dim_
    const float4* samples  = (const float4*)d_in[0];
    const float*  mus_orig = (const float*)d_in[1];
    const float*  mus      = (const float*)d_in[2];
    const float*  psi      = (const float*)d_in[3];
    const int*    idx_symb = (const int*)d_in[4];
    const int*    idx_comp = (const int*)d_in[5];
    float4*       out      = (float4*)d_out;

    // n_samp: both index arrays have n elements; out_size = n * N_DIM as cross-check.
    int n = in_sizes[4];
    if (n <= 1 && n_in > 5) n = in_sizes[5];
    if (out_size > 0 && n != out_size / N_DIM) n = out_size / N_DIM;

    const int groups = (n + RPT - 1) / RPT;
    const int grid = (groups + BLOCK - 1) / BLOCK;  // 8192 at n=8388608

    inv_affine_kernel<<<grid, BLOCK>>>(samples, mus_orig, mus, psi,
                                       idx_symb, idx_comp, out, n);
}

// round 14
// speedup vs baseline: 1.8299x; 1.8299x over previous
#include <cuda_runtime.h>
#include <cstdint>

// AutoencoderInverseAffine: out[n] = (samples[n] - mus[symb,comp]) / psi[comp] + mus_orig[symb,comp]
// One FMA per element: out = s * a[comp] + b[symb,comp],
//   a = 1/psi, b = mus_orig - mus*a  (precomputed in 2.2 KB shared).
//
// R12 post-mortem fix: COALESCED mapping. One float4 chunk (half-row) per thread
// slot, consecutive lanes -> consecutive float4s (4 L1tex wavefronts per warp
// request instead of 32 with the old blocked-row layout). 2 chunks/thread at
// +BLOCK stride for MLP.

#define N_DIM   8
#define N_COMP  4
#define NX      16
#define AD      (N_COMP * N_DIM)        // 32
#define TBL     (NX * AD)               // 512
#define BLOCK   256
#define CPT     2                        // chunks (float4 half-rows) per thread

__global__ void __launch_bounds__(BLOCK)
inv_affine_kernel(const float4* __restrict__ samples,   // 2n float4 chunks
                  const float*  __restrict__ mus_orig,  // 512
                  const float*  __restrict__ mus,       // 512
                  const float*  __restrict__ psi,       // 32
                  const int*    __restrict__ idx_symb,  // n
                  const int*    __restrict__ idx_comp,  // n
                  float4*       __restrict__ out,       // 2n float4 chunks
                  int nchunks)                          // = 2*n
{
    __shared__ __align__(16) float s_a[AD];   // 1/psi          (8 float4)
    __shared__ __align__(16) float s_b[TBL];  // mus_orig - mus/psi (128 float4)

    const int tid = threadIdx.x;

    #pragma unroll
    for (int i = tid; i < TBL; i += BLOCK) {
        const int j = i & (AD - 1);
        const float ip = __frcp_rn(psi[j]);
        s_b[i] = fmaf(-mus[i], ip, mus_orig[i]);
    }
    if (tid < AD) s_a[tid] = __frcp_rn(psi[tid]);
    __syncthreads();

    const int base = blockIdx.x * (CPT * BLOCK) + tid;

    // ---- front-batch the independent global loads for both chunks ----
    const int c0 = base;
    const int c1 = base + BLOCK;
    const bool v0 = (c0 < nchunks);
    const bool v1 = (c1 < nchunks);

    float4 s0, s1;
    int sy0 = 0, cp0 = 0, sy1 = 0, cp1 = 0;

    if (v0) {
        s0  = __ldcs(&samples[c0]);
        sy0 = idx_symb[c0 >> 1];
        cp0 = idx_comp[c0 >> 1];
    }
    if (v1) {
        s1  = __ldcs(&samples[c1]);
        sy1 = idx_symb[c1 >> 1];
        cp1 = idx_comp[c1 >> 1];
    }

    if (v0) {
        const int h0 = (c0 & 1) * 4;
        const float4 a = *(const float4*)&s_a[cp0 * N_DIM + h0];
        const float4 b = *(const float4*)&s_b[sy0 * AD + cp0 * N_DIM + h0];
        float4 o;
        o.x = fmaf(s0.x, a.x, b.x);
        o.y = fmaf(s0.y, a.y, b.y);
        o.z = fmaf(s0.z, a.z, b.z);
        o.w = fmaf(s0.w, a.w, b.w);
        __stcs(&out[c0], o);
    }
    if (v1) {
        const int h1 = (c1 & 1) * 4;
        const float4 a = *(const float4*)&s_a[cp1 * N_DIM + h1];
        const float4 b = *(const float4*)&s_b[sy1 * AD + cp1 * N_DIM + h1];
        float4 o;
        o.x = fmaf(s1.x, a.x, b.x);
        o.y = fmaf(s1.y, a.y, b.y);
        o.z = fmaf(s1.z, a.z, b.z);
        o.w = fmaf(s1.w, a.w, b.w);
        __stcs(&out[c1], o);
    }
}

extern "C" void kernel_launch(void* const* d_in, const int* in_sizes, int n_in,
                              void* d_out, int out_size)
{
    // metadata order: samples_, mus_orig_, mus_, psi_c_, idx_symb_, idx_comp_, n_samp_, n_dim_
    const float4* samples  = (const float4*)d_in[0];
    const float*  mus_orig = (const float*)d_in[1];
    const float*  mus      = (const float*)d_in[2];
    const float*  psi      = (const float*)d_in[3];
    const int*    idx_symb = (const int*)d_in[4];
    const int*    idx_comp = (const int*)d_in[5];
    float4*       out      = (float4*)d_out;

    // n_samp: both index arrays have n elements; out_size = n * N_DIM cross-check.
    int n = in_sizes[4];
    if (n <= 1 && n_in > 5) n = in_sizes[5];
    if (out_size > 0 && n != out_size / N_DIM) n = out_size / N_DIM;

    const int nchunks = 2 * n;                                   // float4 half-rows
    const int grid = (nchunks + CPT * BLOCK - 1) / (CPT * BLOCK); // 32768 at n=8388608

    inv_affine_kernel<<<grid, BLOCK>>>(samples, mus_orig, mus, psi,
                                       idx_symb, idx_comp, out, nchunks);
}